// round 5
// baseline (speedup 1.0000x reference)
#include <cuda_runtime.h>

#define N_ROWS 32768
#define K_ANCH 32
#define D_FEAT 128

// Bit-reversed 5-bit processing order: consecutive items pair at xor-offset 16,
// then 8, 4, 2, 1 — enables eager binary-counter folding with <=6 live partials.
__device__ __constant__ int BREV5[32] = {
     0, 16,  8, 24,  4, 20, 12, 28,
     2, 18, 10, 26,  6, 22, 14, 30,
     1, 17,  9, 25,  5, 21, 13, 29,
     3, 19, 11, 27,  7, 23, 15, 31
};

// Fold two composites at lane-xor offset `off`. `a` must be the composite
// whose k-set has the `off` bit clear (the OLDER one in bit-reversed order).
// After all 5 folds, lane l holds the full cross-lane sum for k == l.
__device__ __forceinline__ float warp_fold(float a, float b, int off, int lane) {
    float r = (lane & off) ? a : b;
    float s = __shfl_xor_sync(0xFFFFFFFFu, r, off);
    return ((lane & off) ? b : a) + s;
}

// Single fused kernel, both branches (blockIdx.y). Warp per row n, float4 lane.
//   os[n,d]  = (1/K) sum_k dm[n,k] * x[idx[n,k], d]
//   op[n,k]  = dm[n,k] * dot(x[idx[n,k],:], w) + b      (via in-register fold)
__global__ __launch_bounds__(256) void fused_kernel(
    const float* __restrict__ x1, const int* __restrict__ idx1, const float* __restrict__ dm1,
    const float* __restrict__ x2, const int* __restrict__ idx2, const float* __restrict__ dm2,
    const float* __restrict__ w,  const float* __restrict__ b_out,
    float* __restrict__ op1, float* __restrict__ os1,
    float* __restrict__ op2, float* __restrict__ os2)
{
    const int br = blockIdx.y;
    const float* __restrict__ x   = br ? x2   : x1;
    const int*   __restrict__ idx = br ? idx2 : idx1;
    const float* __restrict__ dm  = br ? dm2  : dm1;
    float*       __restrict__ op  = br ? op2  : op1;
    float*       __restrict__ os  = br ? os2  : os1;

    const int warp = threadIdx.x >> 5;
    const int lane = threadIdx.x & 31;
    const int n    = blockIdx.x * 8 + warp;
    const unsigned FULL = 0xFFFFFFFFu;

    // Lane l owns metadata for k == l.
    const int   a      = idx[n * K_ANCH + lane];   // coalesced
    const float d      = dm [n * K_ANCH + lane];   // coalesced
    const int   my_off = a * (int)(D_FEAT * sizeof(float));

    // This lane's 4-wide slice of w (broadcast-friendly, L1/const resident).
    const float4 w4 = reinterpret_cast<const float4*>(w)[lane];

    const char* __restrict__ xb = reinterpret_cast<const char*>(x);
    const int lane_byte = lane * 16;

    float4 acc = make_float4(0.f, 0.f, 0.f, 0.f);

    float stk[6];
    int sp = 0;

    #pragma unroll
    for (int i = 0; i < 32; i++) {
        const int k = BREV5[i];
        const int   ok = __shfl_sync(FULL, my_off, k);
        const float dk = __shfl_sync(FULL, d,      k);
        const float4 v = __ldg(reinterpret_cast<const float4*>(xb + ok + lane_byte));

        // t = dk * v : shared by both outputs.
        const float tx = dk * v.x, ty = dk * v.y, tz = dk * v.z, tw = dk * v.w;
        acc.x += tx; acc.y += ty; acc.z += tz; acc.w += tw;

        // per-lane partial of dot(t, w)
        float o = tx * w4.x;
        o = fmaf(ty, w4.y, o);
        o = fmaf(tz, w4.z, o);
        o = fmaf(tw, w4.w, o);

        stk[sp++] = o;

        // Eager binary-counter folding: after item i, fold at depth j iff
        // (i+1) is divisible by 2^(j+1). Fully unrolled -> constant control flow.
        #pragma unroll
        for (int j = 0; j < 5; j++) {
            if (((i + 1) & ((2 << j) - 1)) == 0) {
                const int off = 16 >> j;
                sp -= 2;
                stk[sp] = warp_fold(stk[sp], stk[sp + 1], off, lane);
                sp += 1;
            }
        }
    }

    // stk[0]: fully reduced, lane l holds op-value for k == l (pre-bias).
    const float opv = stk[0] + __ldg(&b_out[0]);

    const float inv = 1.0f / (float)K_ANCH;
    acc.x *= inv; acc.y *= inv; acc.z *= inv; acc.w *= inv;

    reinterpret_cast<float4*>(os)[n * (D_FEAT / 4) + lane] = acc;   // coalesced 512B
    op[n * K_ANCH + lane] = opv;                                    // coalesced 128B
}

extern "C" void kernel_launch(void* const* d_in, const int* in_sizes, int n_in,
                              void* d_out, int out_size) {
    const float* x1   = (const float*)d_in[0];
    const int*   idx1 = (const int*)  d_in[1];
    const float* dm1  = (const float*)d_in[2];
    const float* x2   = (const float*)d_in[3];
    const int*   idx2 = (const int*)  d_in[4];
    const float* dm2  = (const float*)d_in[5];
    const float* w    = (const float*)d_in[6];
    const float* b    = (const float*)d_in[7];

    float* out = (float*)d_out;
    float* op1 = out;                                       // [N, K]
    float* os1 = op1 + (size_t)N_ROWS * K_ANCH;             // [N, D]
    float* op2 = os1 + (size_t)N_ROWS * D_FEAT;             // [N, K]
    float* os2 = op2 + (size_t)N_ROWS * K_ANCH;             // [N, D]

    dim3 gg(N_ROWS / 8, 2);
    fused_kernel<<<gg, 256>>>(x1, idx1, dm1, x2, idx2, dm2, w, b,
                              op1, os1, op2, os2);
}

// round 6
// speedup vs baseline: 1.0717x; 1.0717x over previous
#include <cuda_runtime.h>

#define N_ROWS 32768
#define K_ANCH 32
#define D_FEAT 128

// Fold two composites at lane-xor offset `off`. `a` must be the composite
// whose k-set has the `off` bit clear (the OLDER one in natural order,
// folding LSB-first). After all 5 folds, lane l holds the sum for k == l.
__device__ __forceinline__ float warp_fold(float a, float b, int off, int lane) {
    float r = (lane & off) ? a : b;
    float s = __shfl_xor_sync(0xFFFFFFFFu, r, off);
    return ((lane & off) ? b : a) + s;
}

// Single fused kernel, both branches (blockIdx.y). Warp per row n, float4 lane.
//   os[n,d]  = (1/K) sum_k dm[n,k] * x[idx[n,k], d]
//   op[n,k]  = dm[n,k] * dot(x[idx[n,k],:], w) + b      (in-register fold)
// Metadata broadcast via LDS.128 (1 slot / 2 k's) to minimize LSU-pipe ops.
__global__ __launch_bounds__(256) void fused_kernel(
    const float* __restrict__ x1, const int* __restrict__ idx1, const float* __restrict__ dm1,
    const float* __restrict__ x2, const int* __restrict__ idx2, const float* __restrict__ dm2,
    const float* __restrict__ w,  const float* __restrict__ b_out,
    float* __restrict__ op1, float* __restrict__ os1,
    float* __restrict__ op2, float* __restrict__ os2)
{
    const int br = blockIdx.y;
    const float* __restrict__ x   = br ? x2   : x1;
    const int*   __restrict__ idx = br ? idx2 : idx1;
    const float* __restrict__ dm  = br ? dm2  : dm1;
    float*       __restrict__ op  = br ? op2  : op1;
    float*       __restrict__ os  = br ? os2  : os1;

    const int warp = threadIdx.x >> 5;
    const int lane = threadIdx.x & 31;
    const int n    = blockIdx.x * 8 + warp;

    // Metadata for 2 k's per int4: (off_2p, dm_2p, off_2p+1, dm_2p+1).
    __shared__ int4 s_meta[8][16];

    // Lane l owns metadata for k == l.
    const int   a = idx[n * K_ANCH + lane];    // coalesced
    const float d = dm [n * K_ANCH + lane];    // coalesced

    // Lane l writes 8B at (pair l/2, half l&1): consecutive 8B -> conflict-free STS.64.
    {
        int2* dst = reinterpret_cast<int2*>(&s_meta[warp][0]) + lane;
        *dst = make_int2(a * (int)(D_FEAT * sizeof(float)), __float_as_int(d));
    }
    __syncwarp();

    // This lane's 4-wide slice of w.
    const float4 w4 = reinterpret_cast<const float4*>(w)[lane];

    const char* __restrict__ xb = reinterpret_cast<const char*>(x);
    const int lane_byte = lane * 16;

    float4 acc = make_float4(0.f, 0.f, 0.f, 0.f);

    float stk[6];
    int sp = 0;

    #pragma unroll
    for (int p = 0; p < 16; p++) {
        const int4 m = s_meta[warp][p];          // broadcast LDS.128 (1 slot)
        const float d0 = __int_as_float(m.y);
        const float d1 = __int_as_float(m.w);
        const float4 v0 = __ldg(reinterpret_cast<const float4*>(xb + m.x + lane_byte));
        const float4 v1 = __ldg(reinterpret_cast<const float4*>(xb + m.z + lane_byte));

        // k = 2p
        {
            const float tx = d0 * v0.x, ty = d0 * v0.y, tz = d0 * v0.z, tw = d0 * v0.w;
            acc.x += tx; acc.y += ty; acc.z += tz; acc.w += tw;
            float o = tx * w4.x;
            o = fmaf(ty, w4.y, o); o = fmaf(tz, w4.z, o); o = fmaf(tw, w4.w, o);
            stk[sp++] = o;
        }
        // k = 2p+1
        {
            const float tx = d1 * v1.x, ty = d1 * v1.y, tz = d1 * v1.z, tw = d1 * v1.w;
            acc.x += tx; acc.y += ty; acc.z += tz; acc.w += tw;
            float o = tx * w4.x;
            o = fmaf(ty, w4.y, o); o = fmaf(tz, w4.z, o); o = fmaf(tw, w4.w, o);
            stk[sp++] = o;
        }

        // Eager binary-counter folding over natural k order, LSB-first:
        // after item i (i = 2p+1 here), fold depth j iff (i+1) % 2^(j+1) == 0.
        const int i1 = 2 * p + 2;   // items completed
        #pragma unroll
        for (int j = 0; j < 5; j++) {
            if ((i1 & ((2 << j) - 1)) == 0) {
                const int off = 1 << j;
                sp -= 2;
                stk[sp] = warp_fold(stk[sp], stk[sp + 1], off, lane);
                sp += 1;
            }
        }
    }

    // stk[0]: lane l holds op-value for k == l (pre-bias).
    const float opv = stk[0] + __ldg(&b_out[0]);

    const float inv = 1.0f / (float)K_ANCH;
    acc.x *= inv; acc.y *= inv; acc.z *= inv; acc.w *= inv;

    reinterpret_cast<float4*>(os)[n * (D_FEAT / 4) + lane] = acc;   // coalesced 512B
    op[n * K_ANCH + lane] = opv;                                    // coalesced 128B
}

extern "C" void kernel_launch(void* const* d_in, const int* in_sizes, int n_in,
                              void* d_out, int out_size) {
    const float* x1   = (const float*)d_in[0];
    const int*   idx1 = (const int*)  d_in[1];
    const float* dm1  = (const float*)d_in[2];
    const float* x2   = (const float*)d_in[3];
    const int*   idx2 = (const int*)  d_in[4];
    const float* dm2  = (const float*)d_in[5];
    const float* w    = (const float*)d_in[6];
    const float* b    = (const float*)d_in[7];

    float* out = (float*)d_out;
    float* op1 = out;                                       // [N, K]
    float* os1 = op1 + (size_t)N_ROWS * K_ANCH;             // [N, D]
    float* op2 = os1 + (size_t)N_ROWS * D_FEAT;             // [N, K]
    float* os2 = op2 + (size_t)N_ROWS * K_ANCH;             // [N, D]

    dim3 gg(N_ROWS / 8, 2);
    fused_kernel<<<gg, 256>>>(x1, idx1, dm1, x2, idx2, dm2, w, b,
                              op1, os1, op2, os2);
}